// round 13
// baseline (speedup 1.0000x reference)
#include <cuda_runtime.h>
#include <cuda_fp16.h>

#define N_NODES 50000
#define N_EDGES 1600000
#define HF 128
#define NC 16

// -------- scratch (device globals; no allocation allowed) --------
__device__ __half g_ft16[N_NODES * HF];   // post-GEMM features (layers 1/2), fp16
__device__ __half g_ftc[N_NODES * NC];    // layer-3 features, fp16
__device__ __half g_h[N_NODES * HF];      // layer outputs (fp16)
__device__ float  g_el[N_NODES];
__device__ float  g_er[N_NODES];
__device__ int    g_off[N_NODES + 1];
__device__ int    g_pos[N_NODES];         // zero-init at load; re-zeroed by agg128
__device__ unsigned short g_csrc[N_EDGES]; // src ids fit in 16 bits
__device__ int    g_bsum[256];
__device__ __half g_wt1[HF * HF];         // W1^T fp16 [n][k]
__device__ __half g_wt2[HF * HF];         // W2^T fp16 [n][k]

// ============ fused: W transpose/convert (blocks 0-63) + hist (rest) =======
__global__ void whist_kernel(const float* __restrict__ W1, const float* __restrict__ W2,
                             __half* __restrict__ Wt1, __half* __restrict__ Wt2,
                             const int* __restrict__ dst, int* __restrict__ cnt, int E) {
    if (blockIdx.x < 64) {
        int i = blockIdx.x * 256 + threadIdx.x;
        int nn = i >> 7, k = i & 127;
        Wt1[nn * 128 + k] = __float2half_rn(W1[k * 128 + nn]);
        Wt2[nn * 128 + k] = __float2half_rn(W2[k * 128 + nn]);
        return;
    }
    int bid = blockIdx.x - 64;
    int nb = gridDim.x - 64;
    int E4 = E >> 2;
    const int4* d4 = (const int4*)dst;
    for (int i = bid * blockDim.x + threadIdx.x; i < E4; i += nb * blockDim.x) {
        int4 d = __ldg(&d4[i]);
        atomicAdd(&cnt[d.x], 1);
        atomicAdd(&cnt[d.y], 1);
        atomicAdd(&cnt[d.z], 1);
        atomicAdd(&cnt[d.w], 1);
    }
    int base = E4 << 2;
    int t = bid * blockDim.x + threadIdx.x;
    if (t < (E - base)) atomicAdd(&cnt[dst[base + t]], 1);
}

// ======================= CSR build =======================

__global__ void scan1_kernel(const int* __restrict__ cnt, int* __restrict__ off,
                             int* __restrict__ bsum, int n) {
    __shared__ int wsum[32];
    int tid = threadIdx.x;
    int i = blockIdx.x * 1024 + tid;
    int lane = tid & 31, wid = tid >> 5;
    int v = (i < n) ? cnt[i] : 0;
    int x = v;
    #pragma unroll
    for (int d = 1; d < 32; d <<= 1) {
        int y = __shfl_up_sync(0xffffffffu, x, d);
        if (lane >= d) x += y;
    }
    if (lane == 31) wsum[wid] = x;
    __syncthreads();
    if (wid == 0) {
        int w = wsum[lane];
        #pragma unroll
        for (int d = 1; d < 32; d <<= 1) {
            int y = __shfl_up_sync(0xffffffffu, w, d);
            if (lane >= d) w += y;
        }
        wsum[lane] = w;
    }
    __syncthreads();
    int excl = x - v + (wid > 0 ? wsum[wid - 1] : 0);
    if (i < n) off[i] = excl;
    if (tid == 0) bsum[blockIdx.x] = wsum[31];
}

// phase 2+3 fused: each block locally scans bsum (nb<=64), then adds
__global__ void scan3_kernel(int* __restrict__ off, int* __restrict__ pos,
                             const int* __restrict__ bsum, int n, int nb) {
    __shared__ int sprefix;
    __shared__ int stotal;
    int tid = threadIdx.x;
    if (tid < 32) {
        int v0 = (tid < nb) ? bsum[tid] : 0;
        int v1 = (tid + 32 < nb) ? bsum[tid + 32] : 0;
        int x0 = v0;
        #pragma unroll
        for (int d = 1; d < 32; d <<= 1) {
            int y = __shfl_up_sync(0xffffffffu, x0, d);
            if ((tid & 31) >= d) x0 += y;
        }
        int sum0 = __shfl_sync(0xffffffffu, x0, 31);
        int x1 = v1;
        #pragma unroll
        for (int d = 1; d < 32; d <<= 1) {
            int y = __shfl_up_sync(0xffffffffu, x1, d);
            if ((tid & 31) >= d) x1 += y;
        }
        int sum1 = __shfl_sync(0xffffffffu, x1, 31);
        int b = blockIdx.x;
        int excl;
        if (b < 32) excl = __shfl_sync(0xffffffffu, x0 - v0, b);
        else        excl = sum0 + __shfl_sync(0xffffffffu, x1 - v1, b - 32);
        if (tid == 0) { sprefix = excl; stotal = sum0 + sum1; }
    }
    __syncthreads();
    int add = sprefix;
    int i = blockIdx.x * 1024 + tid;
    if (i < n) {
        int v = off[i] + add;
        off[i] = v;
        pos[i] = v;
    }
    if (blockIdx.x == 0 && tid == 0) off[n] = stotal;
}

__global__ void scatter_kernel(const int* __restrict__ src, const int* __restrict__ dst,
                               int* __restrict__ pos, unsigned short* __restrict__ csrc, int E) {
    int E4 = E >> 2;
    const int4* s4 = (const int4*)src;
    const int4* d4 = (const int4*)dst;
    for (int i = blockIdx.x * blockDim.x + threadIdx.x; i < E4; i += gridDim.x * blockDim.x) {
        int4 s = __ldg(&s4[i]);
        int4 d = __ldg(&d4[i]);
        int p0 = atomicAdd(&pos[d.x], 1);
        int p1 = atomicAdd(&pos[d.y], 1);
        int p2 = atomicAdd(&pos[d.z], 1);
        int p3 = atomicAdd(&pos[d.w], 1);
        csrc[p0] = (unsigned short)s.x;
        csrc[p1] = (unsigned short)s.y;
        csrc[p2] = (unsigned short)s.z;
        csrc[p3] = (unsigned short)s.w;
    }
    int base = E4 << 2;
    int t = blockIdx.x * blockDim.x + threadIdx.x;
    if (t < (E - base)) {
        int p = atomicAdd(&pos[dst[base + t]], 1);
        csrc[p] = (unsigned short)src[base + t];
    }
}

// ========== GEMM 128x128 via HMMA, 512 threads (16 warps, 16x64 warp tile) =
#define SA 136
#define SB 136
#define GEMM_SMEM ((128 * SA + 128 * SB) * 2)

__device__ __forceinline__ void mma16816(float& d0, float& d1, float& d2, float& d3,
                                         unsigned a0, unsigned a1, unsigned a2, unsigned a3,
                                         unsigned b0, unsigned b1) {
    asm volatile("mma.sync.aligned.m16n8k16.row.col.f32.f16.f16.f32 "
                 "{%0,%1,%2,%3}, {%4,%5,%6,%7}, {%8,%9}, {%0,%1,%2,%3};"
                 : "+f"(d0), "+f"(d1), "+f"(d2), "+f"(d3)
                 : "r"(a0), "r"(a1), "r"(a2), "r"(a3), "r"(b0), "r"(b1));
}

template <typename T>
__global__ void __launch_bounds__(512, 2) gemm128_kernel(
    const T* __restrict__ A, const __half* __restrict__ Wt,
    const float* __restrict__ al, const float* __restrict__ ar,
    __half* __restrict__ C16, float* __restrict__ el, float* __restrict__ er, int M) {
    extern __shared__ __half smh[];
    __half* As = smh;              // [m][k], stride SA
    __half* Bs = smh + 128 * SA;   // [n][k], stride SB
    __shared__ float redl[16][16];
    __shared__ float redr[16][16];
    int tid = threadIdx.x;
    int row0 = blockIdx.x * 128;

    // stage Wt (fp16 global, coalesced 16B)
    for (int i = tid; i < 2048; i += 512) {
        int n = i >> 4, k8 = (i & 15) * 8;
        uint4 v = *(const uint4*)(Wt + n * 128 + k8);
        *(uint4*)(Bs + n * SB + k8) = v;
    }
    // stage A
    if (sizeof(T) == 4) {          // fp32 input: convert while staging
        const float* Af = (const float*)A;
        for (int i = tid; i < 4096; i += 512) {
            int r = i >> 5, c = (i & 31) * 4;
            int gr = row0 + r;
            float4 v = make_float4(0.f, 0.f, 0.f, 0.f);
            if (gr < M) v = *(const float4*)(Af + gr * 128 + c);
            *(__half2*)(As + r * SA + c)     = __float22half2_rn(make_float2(v.x, v.y));
            *(__half2*)(As + r * SA + c + 2) = __float22half2_rn(make_float2(v.z, v.w));
        }
    } else {                       // fp16 input: straight 16B copy
        const __half* Ah = (const __half*)A;
        for (int i = tid; i < 2048; i += 512) {
            int r = i >> 4, c = (i & 15) * 8;
            int gr = row0 + r;
            uint4 v = make_uint4(0u, 0u, 0u, 0u);
            if (gr < M) v = *(const uint4*)(Ah + gr * 128 + c);
            *(uint4*)(As + r * SA + c) = v;
        }
    }
    __syncthreads();

    int w = tid >> 5, lane = tid & 31;
    int g = lane >> 2, tg = lane & 3;
    int mr = (w >> 1) * 16;        // 8 m-groups of 16 rows
    int nc0 = (w & 1) * 64;        // 2 n-groups of 64 cols

    float acc[8][4];
    #pragma unroll
    for (int nt = 0; nt < 8; nt++)
        #pragma unroll
        for (int j = 0; j < 4; j++) acc[nt][j] = 0.f;

    const __half* ap0 = As + (mr + g) * SA + 2 * tg;
    const __half* ap1 = ap0 + 8 * SA;
    const __half* bp  = Bs + (nc0 + g) * SB + 2 * tg;

    #pragma unroll
    for (int ks = 0; ks < 128; ks += 16) {
        unsigned a0 = *(const unsigned*)(ap0 + ks);
        unsigned a1 = *(const unsigned*)(ap1 + ks);
        unsigned a2 = *(const unsigned*)(ap0 + ks + 8);
        unsigned a3 = *(const unsigned*)(ap1 + ks + 8);
        #pragma unroll
        for (int nt = 0; nt < 8; nt++) {
            unsigned b0 = *(const unsigned*)(bp + nt * 8 * SB + ks);
            unsigned b1 = *(const unsigned*)(bp + nt * 8 * SB + ks + 8);
            mma16816(acc[nt][0], acc[nt][1], acc[nt][2], acc[nt][3],
                     a0, a1, a2, a3, b0, b1);
        }
    }

    int row_a = row0 + mr + g;
    int row_b = row_a + 8;
    float sl0 = 0.f, sr0 = 0.f, sl1 = 0.f, sr1 = 0.f;
    #pragma unroll
    for (int nt = 0; nt < 8; nt++) {
        int c0 = nc0 + nt * 8 + 2 * tg;
        float av0 = __ldg(&al[c0]), av1 = __ldg(&al[c0 + 1]);
        float rv0 = __ldg(&ar[c0]), rv1 = __ldg(&ar[c0 + 1]);
        sl0 += acc[nt][0] * av0 + acc[nt][1] * av1;
        sr0 += acc[nt][0] * rv0 + acc[nt][1] * rv1;
        sl1 += acc[nt][2] * av0 + acc[nt][3] * av1;
        sr1 += acc[nt][2] * rv0 + acc[nt][3] * rv1;
        if (row_a < M)
            *(__half2*)(C16 + row_a * 128 + c0) =
                __float22half2_rn(make_float2(acc[nt][0], acc[nt][1]));
        if (row_b < M)
            *(__half2*)(C16 + row_b * 128 + c0) =
                __float22half2_rn(make_float2(acc[nt][2], acc[nt][3]));
    }
    #pragma unroll
    for (int d = 1; d < 4; d <<= 1) {
        sl0 += __shfl_xor_sync(0xffffffffu, sl0, d);
        sr0 += __shfl_xor_sync(0xffffffffu, sr0, d);
        sl1 += __shfl_xor_sync(0xffffffffu, sl1, d);
        sr1 += __shfl_xor_sync(0xffffffffu, sr1, d);
    }
    if (tg == 0) {
        redl[w][g] = sl0; redl[w][g + 8] = sl1;
        redr[w][g] = sr0; redr[w][g + 8] = sr1;
    }
    __syncthreads();
    if ((w & 1) == 0 && lane < 16) {
        int row = row0 + mr + lane;
        if (row < M) {
            el[row] = redl[w][lane] + redl[w + 1][lane];
            er[row] = redr[w][lane] + redr[w + 1][lane];
        }
    }
}

// ======================= aggregation H=128: chunked, warp per node =========
__global__ void agg128_kernel(const __half* __restrict__ ft, const float* __restrict__ el,
                              const float* __restrict__ er, const int* __restrict__ off,
                              const unsigned short* __restrict__ csrc,
                              const float* __restrict__ bias,
                              __half* __restrict__ out, int* __restrict__ pos, int n) {
    int gw = (blockIdx.x * blockDim.x + threadIdx.x) >> 5;
    if (gw >= n) return;
    int lane = threadIdx.x & 31;
    if (lane == 0) pos[gw] = 0;              // re-zero for next replay's hist
    int beg = off[gw], end = off[gw + 1];
    float erd = __ldg(&er[gw]);
    float ssum = 0.f;
    float4 acc = make_float4(0.f, 0.f, 0.f, 0.f);
    const float2* fb = (const float2*)ft;

    int j0 = beg;
    for (; j0 + 32 <= end; j0 += 32) {
        int sidx = (int)__ldg(&csrc[j0 + lane]);
        float e = __ldg(&el[sidx]) + erd;
        e = fmaxf(e, 0.2f * e);
        float w = __expf(e);
        ssum += w;
        #pragma unroll
        for (int t = 0; t < 32; t++) {
            float wt = __shfl_sync(0xffffffffu, w, t);
            int st = __shfl_sync(0xffffffffu, sidx, t);
            float2 p = __ldg(&fb[st * 32 + lane]);
            __half2 h0 = *(__half2*)&p.x;
            __half2 h1 = *(__half2*)&p.y;
            float2 f0 = __half22float2(h0);
            float2 f1 = __half22float2(h1);
            acc.x = fmaf(wt, f0.x, acc.x);
            acc.y = fmaf(wt, f0.y, acc.y);
            acc.z = fmaf(wt, f1.x, acc.z);
            acc.w = fmaf(wt, f1.y, acc.w);
        }
    }
    int rem = end - j0;
    if (rem > 0) {
        int sidx = 0; float w = 0.f;
        if (lane < rem) {
            sidx = (int)__ldg(&csrc[j0 + lane]);
            float e = __ldg(&el[sidx]) + erd;
            e = fmaxf(e, 0.2f * e);
            w = __expf(e);
        }
        ssum += w;
        for (int t = 0; t < rem; t++) {
            float wt = __shfl_sync(0xffffffffu, w, t);
            int st = __shfl_sync(0xffffffffu, sidx, t);
            float2 p = __ldg(&fb[st * 32 + lane]);
            __half2 h0 = *(__half2*)&p.x;
            __half2 h1 = *(__half2*)&p.y;
            float2 f0 = __half22float2(h0);
            float2 f1 = __half22float2(h1);
            acc.x = fmaf(wt, f0.x, acc.x);
            acc.y = fmaf(wt, f0.y, acc.y);
            acc.z = fmaf(wt, f1.x, acc.z);
            acc.w = fmaf(wt, f1.y, acc.w);
        }
    }
    #pragma unroll
    for (int d = 16; d; d >>= 1) ssum += __shfl_xor_sync(0xffffffffu, ssum, d);
    float inv = (ssum > 0.f) ? 1.f / ssum : 0.f;
    float4 bv = ((const float4*)bias)[lane];
    __half2 o0 = __float22half2_rn(make_float2(fmaxf(acc.x * inv + bv.x, 0.f),
                                               fmaxf(acc.y * inv + bv.y, 0.f)));
    __half2 o1 = __float22half2_rn(make_float2(fmaxf(acc.z * inv + bv.z, 0.f),
                                               fmaxf(acc.w * inv + bv.w, 0.f)));
    uint2 u;
    u.x = *(unsigned*)&o0; u.y = *(unsigned*)&o1;
    *(uint2*)(out + gw * 128 + lane * 4) = u;
}

// ======================= layer 3: GEMM 128->16 (A fp16) ==================
__global__ void __launch_bounds__(256) gemm16_kernel(const __half* __restrict__ A,
                                                     const float* __restrict__ W,
                                                     const float* __restrict__ al,
                                                     const float* __restrict__ ar,
                                                     __half* __restrict__ C16,
                                                     float* __restrict__ el,
                                                     float* __restrict__ er, int M) {
    __shared__ float Ws[128 * 16];
    __shared__ float As[16 * 128];
    __shared__ float als[16], ars[16];
    int tid = threadIdx.x;
    for (int i = tid; i < 2048; i += 256) Ws[i] = W[i];
    if (tid < 16) { als[tid] = al[tid]; ars[tid] = ar[tid]; }
    int node0 = blockIdx.x * 16;
    for (int i = tid; i < 1024; i += 256) {   // 16 rows x 64 half2
        int ln = i >> 6, c2 = i & 63;
        int node = node0 + ln;
        float2 v = make_float2(0.f, 0.f);
        if (node < M) v = __half22float2(*(const __half2*)(A + node * 128 + c2 * 2));
        *(float2*)(As + ln * 128 + c2 * 2) = v;
    }
    __syncthreads();
    int ln = tid >> 4, col = tid & 15;
    int node = node0 + ln;
    float acc = 0.f;
    #pragma unroll 8
    for (int k = 0; k < 128; k++)
        acc = fmaf(As[ln * 128 + k], Ws[k * 16 + col], acc);

    if (node < M) C16[node * 16 + col] = __float2half_rn(acc);
    float sl = acc * als[col];
    float sr = acc * ars[col];
    #pragma unroll
    for (int d = 1; d < 16; d <<= 1) {
        sl += __shfl_xor_sync(0xffffffffu, sl, d);
        sr += __shfl_xor_sync(0xffffffffu, sr, d);
    }
    if (col == 0 && node < M) { el[node] = sl; er[node] = sr; }
}

// ======================= aggregation NC=16 =======================
__global__ void agg16_kernel(const __half* __restrict__ ftc, const float* __restrict__ el,
                             const float* __restrict__ er, const int* __restrict__ off,
                             const unsigned short* __restrict__ csrc,
                             const float* __restrict__ bias,
                             float* __restrict__ out, int n) {
    int gw = (blockIdx.x * blockDim.x + threadIdx.x) >> 5;
    if (gw >= n) return;
    int lane = threadIdx.x & 31;
    int lh = lane & 15, sel = lane >> 4;
    int beg = off[gw], end = off[gw + 1];
    float erd = __ldg(&er[gw]);
    float ssum = 0.f, acc = 0.f;

    int j0 = beg;
    for (; j0 + 32 <= end; j0 += 32) {
        int sidx = (int)__ldg(&csrc[j0 + lane]);
        float e = __ldg(&el[sidx]) + erd;
        e = fmaxf(e, 0.2f * e);
        float w = __expf(e);
        ssum += w;
        #pragma unroll
        for (int t = 0; t < 32; t += 2) {
            int tt = t + sel;
            float wt = __shfl_sync(0xffffffffu, w, tt);
            int st = __shfl_sync(0xffffffffu, sidx, tt);
            float f = __half2float(__ldg(&ftc[st * 16 + lh]));
            acc = fmaf(wt, f, acc);
        }
    }
    int rem = end - j0;
    if (rem > 0) {
        int sidx = 0; float w = 0.f;
        if (lane < rem) {
            sidx = (int)__ldg(&csrc[j0 + lane]);
            float e = __ldg(&el[sidx]) + erd;
            e = fmaxf(e, 0.2f * e);
            w = __expf(e);
        }
        ssum += w;
        for (int t = 0; t < rem; t += 2) {
            int tt = t + sel;                 // tt may be == rem: its w is 0
            float wt = __shfl_sync(0xffffffffu, w, tt & 31);
            int st = __shfl_sync(0xffffffffu, sidx, tt & 31);
            float f = __half2float(__ldg(&ftc[st * 16 + lh]));
            acc = fmaf(wt, f, acc);
        }
    }
    #pragma unroll
    for (int d = 16; d; d >>= 1) ssum += __shfl_xor_sync(0xffffffffu, ssum, d);
    acc += __shfl_xor_sync(0xffffffffu, acc, 16);
    float inv = (ssum > 0.f) ? 1.f / ssum : 0.f;
    if (lane < 16)
        out[gw * 16 + lane] = fmaxf(acc * inv + bias[lane], 0.f);
}

// ======================= launch =======================
extern "C" void kernel_launch(void* const* d_in, const int* in_sizes, int n_in,
                              void* d_out, int out_size) {
    const float* feat = (const float*)d_in[0];
    const int*   src  = (const int*)d_in[1];
    const int*   dst  = (const int*)d_in[2];
    const float* W1   = (const float*)d_in[3];
    const float* al1  = (const float*)d_in[4];
    const float* ar1  = (const float*)d_in[5];
    const float* b1   = (const float*)d_in[6];
    const float* W2   = (const float*)d_in[7];
    const float* al2  = (const float*)d_in[8];
    const float* ar2  = (const float*)d_in[9];
    const float* b2   = (const float*)d_in[10];
    const float* W3   = (const float*)d_in[11];
    const float* al3  = (const float*)d_in[12];
    const float* ar3  = (const float*)d_in[13];
    const float* b3   = (const float*)d_in[14];

    int M = in_sizes[0] / HF;
    int E = in_sizes[1];

    __half *ft16, *ftc, *h, *wt1, *wt2;
    float *el, *er;
    int *off, *pos, *bsum;
    unsigned short *csrc;
    cudaGetSymbolAddress((void**)&ft16, g_ft16);
    cudaGetSymbolAddress((void**)&ftc,  g_ftc);
    cudaGetSymbolAddress((void**)&h,    g_h);
    cudaGetSymbolAddress((void**)&el,   g_el);
    cudaGetSymbolAddress((void**)&er,   g_er);
    cudaGetSymbolAddress((void**)&off,  g_off);
    cudaGetSymbolAddress((void**)&pos,  g_pos);
    cudaGetSymbolAddress((void**)&csrc, g_csrc);
    cudaGetSymbolAddress((void**)&bsum, g_bsum);
    cudaGetSymbolAddress((void**)&wt1,  g_wt1);
    cudaGetSymbolAddress((void**)&wt2,  g_wt2);

    cudaFuncSetAttribute(gemm128_kernel<float>,
                         cudaFuncAttributeMaxDynamicSharedMemorySize, GEMM_SMEM);
    cudaFuncSetAttribute(gemm128_kernel<__half>,
                         cudaFuncAttributeMaxDynamicSharedMemorySize, GEMM_SMEM);

    int nb = (M + 1023) / 1024;
    int gemm_blocks = (M + 127) / 128;
    int warp_blocks = (M * 32 + 255) / 256;

    // 0: fused wconv + hist (pos zeroed by previous replay's agg128 / module init)
    whist_kernel<<<64 + 1536, 256>>>(W1, W2, wt1, wt2, dst, pos, E);
    // 1: scan phase 1
    scan1_kernel<<<nb, 1024>>>(pos, off, bsum, M);
    // 2: scan phases 2+3 fused
    scan3_kernel<<<nb, 1024>>>(off, pos, bsum, M, nb);
    // 3: layer-1 GEMM — ncu's profiled slot
    gemm128_kernel<float><<<gemm_blocks, 512, GEMM_SMEM>>>(feat, wt1, al1, ar1, ft16, el, er, M);
    // 4: scatter
    scatter_kernel<<<1600, 256>>>(src, dst, pos, csrc, E);
    // 5: layer-1 aggregation (also re-zeroes pos)
    agg128_kernel<<<warp_blocks, 256>>>(ft16, el, er, off, csrc, b1, h, pos, M);
    // 6-7: layer 2
    gemm128_kernel<__half><<<gemm_blocks, 512, GEMM_SMEM>>>(h, wt2, al2, ar2, ft16, el, er, M);
    agg128_kernel<<<warp_blocks, 256>>>(ft16, el, er, off, csrc, b2, h, pos, M);
    // 8-9: layer 3
    gemm16_kernel<<<(M + 15) / 16, 256>>>(h, W3, al3, ar3, ftc, el, er, M);
    agg16_kernel<<<warp_blocks, 256>>>(ftc, el, er, off, csrc, b3, (float*)d_out, M);
}

// round 14
// speedup vs baseline: 1.0024x; 1.0024x over previous
#include <cuda_runtime.h>
#include <cuda_fp16.h>

#define N_NODES 50000
#define N_EDGES 1600000
#define HF 128
#define NC 16

// -------- scratch (device globals; no allocation allowed) --------
__device__ __half g_ft16[N_NODES * HF];   // post-GEMM features (layers 1/2), fp16
__device__ __half g_ftc[N_NODES * NC];    // layer-3 features, fp16
__device__ __half g_h[N_NODES * HF];      // layer outputs (fp16)
__device__ float  g_el[N_NODES];
__device__ float  g_er[N_NODES];
__device__ int    g_off[N_NODES + 1];
__device__ int    g_pos[N_NODES];         // zero-init at load; re-zeroed by agg128
__device__ unsigned short g_csrc[N_EDGES]; // src ids fit in 16 bits
__device__ int    g_bsum[256];
__device__ __half g_wt1[HF * HF];         // W1^T fp16 [n][k]
__device__ __half g_wt2[HF * HF];         // W2^T fp16 [n][k]

// ============ fused: W transpose/convert (blocks 0-63) + hist (rest) =======
__global__ void whist_kernel(const float* __restrict__ W1, const float* __restrict__ W2,
                             __half* __restrict__ Wt1, __half* __restrict__ Wt2,
                             const int* __restrict__ dst, int* __restrict__ cnt, int E) {
    if (blockIdx.x < 64) {
        int i = blockIdx.x * 256 + threadIdx.x;
        int nn = i >> 7, k = i & 127;
        Wt1[nn * 128 + k] = __float2half_rn(W1[k * 128 + nn]);
        Wt2[nn * 128 + k] = __float2half_rn(W2[k * 128 + nn]);
        return;
    }
    int bid = blockIdx.x - 64;
    int nb = gridDim.x - 64;
    int E4 = E >> 2;
    const int4* d4 = (const int4*)dst;
    for (int i = bid * blockDim.x + threadIdx.x; i < E4; i += nb * blockDim.x) {
        int4 d = __ldg(&d4[i]);
        atomicAdd(&cnt[d.x], 1);
        atomicAdd(&cnt[d.y], 1);
        atomicAdd(&cnt[d.z], 1);
        atomicAdd(&cnt[d.w], 1);
    }
    int base = E4 << 2;
    int t = bid * blockDim.x + threadIdx.x;
    if (t < (E - base)) atomicAdd(&cnt[dst[base + t]], 1);
}

// ======================= CSR build =======================

__global__ void scan1_kernel(const int* __restrict__ cnt, int* __restrict__ off,
                             int* __restrict__ bsum, int n) {
    __shared__ int wsum[32];
    int tid = threadIdx.x;
    int i = blockIdx.x * 1024 + tid;
    int lane = tid & 31, wid = tid >> 5;
    int v = (i < n) ? cnt[i] : 0;
    int x = v;
    #pragma unroll
    for (int d = 1; d < 32; d <<= 1) {
        int y = __shfl_up_sync(0xffffffffu, x, d);
        if (lane >= d) x += y;
    }
    if (lane == 31) wsum[wid] = x;
    __syncthreads();
    if (wid == 0) {
        int w = wsum[lane];
        #pragma unroll
        for (int d = 1; d < 32; d <<= 1) {
            int y = __shfl_up_sync(0xffffffffu, w, d);
            if (lane >= d) w += y;
        }
        wsum[lane] = w;
    }
    __syncthreads();
    int excl = x - v + (wid > 0 ? wsum[wid - 1] : 0);
    if (i < n) off[i] = excl;
    if (tid == 0) bsum[blockIdx.x] = wsum[31];
}

// phase 2+3 fused: each block locally scans bsum (nb<=64), then adds
__global__ void scan3_kernel(int* __restrict__ off, int* __restrict__ pos,
                             const int* __restrict__ bsum, int n, int nb) {
    __shared__ int sprefix;
    __shared__ int stotal;
    int tid = threadIdx.x;
    if (tid < 32) {
        int v0 = (tid < nb) ? bsum[tid] : 0;
        int v1 = (tid + 32 < nb) ? bsum[tid + 32] : 0;
        int x0 = v0;
        #pragma unroll
        for (int d = 1; d < 32; d <<= 1) {
            int y = __shfl_up_sync(0xffffffffu, x0, d);
            if ((tid & 31) >= d) x0 += y;
        }
        int sum0 = __shfl_sync(0xffffffffu, x0, 31);
        int x1 = v1;
        #pragma unroll
        for (int d = 1; d < 32; d <<= 1) {
            int y = __shfl_up_sync(0xffffffffu, x1, d);
            if ((tid & 31) >= d) x1 += y;
        }
        int sum1 = __shfl_sync(0xffffffffu, x1, 31);
        int b = blockIdx.x;
        int excl;
        if (b < 32) excl = __shfl_sync(0xffffffffu, x0 - v0, b);
        else        excl = sum0 + __shfl_sync(0xffffffffu, x1 - v1, b - 32);
        if (tid == 0) { sprefix = excl; stotal = sum0 + sum1; }
    }
    __syncthreads();
    int add = sprefix;
    int i = blockIdx.x * 1024 + tid;
    if (i < n) {
        int v = off[i] + add;
        off[i] = v;
        pos[i] = v;
    }
    if (blockIdx.x == 0 && tid == 0) off[n] = stotal;
}

__global__ void scatter_kernel(const int* __restrict__ src, const int* __restrict__ dst,
                               int* __restrict__ pos, unsigned short* __restrict__ csrc, int E) {
    int E4 = E >> 2;
    const int4* s4 = (const int4*)src;
    const int4* d4 = (const int4*)dst;
    for (int i = blockIdx.x * blockDim.x + threadIdx.x; i < E4; i += gridDim.x * blockDim.x) {
        int4 s = __ldg(&s4[i]);
        int4 d = __ldg(&d4[i]);
        int p0 = atomicAdd(&pos[d.x], 1);
        int p1 = atomicAdd(&pos[d.y], 1);
        int p2 = atomicAdd(&pos[d.z], 1);
        int p3 = atomicAdd(&pos[d.w], 1);
        csrc[p0] = (unsigned short)s.x;
        csrc[p1] = (unsigned short)s.y;
        csrc[p2] = (unsigned short)s.z;
        csrc[p3] = (unsigned short)s.w;
    }
    int base = E4 << 2;
    int t = blockIdx.x * blockDim.x + threadIdx.x;
    if (t < (E - base)) {
        int p = atomicAdd(&pos[dst[base + t]], 1);
        csrc[p] = (unsigned short)src[base + t];
    }
}

// ===== GEMM 128x128 via HMMA, 256 threads, 32x64 warp tile (24 LDS/kstep) ==
#define SA 136
#define SB 136
#define GEMM_SMEM ((128 * SA + 128 * SB) * 2)

__device__ __forceinline__ void mma16816(float& d0, float& d1, float& d2, float& d3,
                                         unsigned a0, unsigned a1, unsigned a2, unsigned a3,
                                         unsigned b0, unsigned b1) {
    asm volatile("mma.sync.aligned.m16n8k16.row.col.f32.f16.f16.f32 "
                 "{%0,%1,%2,%3}, {%4,%5,%6,%7}, {%8,%9}, {%0,%1,%2,%3};"
                 : "+f"(d0), "+f"(d1), "+f"(d2), "+f"(d3)
                 : "r"(a0), "r"(a1), "r"(a2), "r"(a3), "r"(b0), "r"(b1));
}

template <typename T>
__global__ void __launch_bounds__(256) gemm128_kernel(
    const T* __restrict__ A, const __half* __restrict__ Wt,
    const float* __restrict__ al, const float* __restrict__ ar,
    __half* __restrict__ C16, float* __restrict__ el, float* __restrict__ er, int M) {
    extern __shared__ __half smh[];
    __half* As = smh;              // [m][k], stride SA
    __half* Bs = smh + 128 * SA;   // [n][k], stride SB
    __shared__ float redl[8][32];
    __shared__ float redr[8][32];
    int tid = threadIdx.x;
    int row0 = blockIdx.x * 128;

    // stage Wt (fp16 global, coalesced 16B)
    for (int i = tid; i < 2048; i += 256) {
        int n = i >> 4, k8 = (i & 15) * 8;
        uint4 v = *(const uint4*)(Wt + n * 128 + k8);
        *(uint4*)(Bs + n * SB + k8) = v;
    }
    // stage A
    if (sizeof(T) == 4) {          // fp32 input: convert while staging
        const float* Af = (const float*)A;
        for (int i = tid; i < 4096; i += 256) {
            int r = i >> 5, c = (i & 31) * 4;
            int gr = row0 + r;
            float4 v = make_float4(0.f, 0.f, 0.f, 0.f);
            if (gr < M) v = *(const float4*)(Af + gr * 128 + c);
            *(__half2*)(As + r * SA + c)     = __float22half2_rn(make_float2(v.x, v.y));
            *(__half2*)(As + r * SA + c + 2) = __float22half2_rn(make_float2(v.z, v.w));
        }
    } else {                       // fp16 input: straight 16B copy
        const __half* Ah = (const __half*)A;
        for (int i = tid; i < 2048; i += 256) {
            int r = i >> 4, c = (i & 15) * 8;
            int gr = row0 + r;
            uint4 v = make_uint4(0u, 0u, 0u, 0u);
            if (gr < M) v = *(const uint4*)(Ah + gr * 128 + c);
            *(uint4*)(As + r * SA + c) = v;
        }
    }
    __syncthreads();

    int w = tid >> 5, lane = tid & 31;
    int g = lane >> 2, tg = lane & 3;
    int mr = (w >> 1) * 32;        // 4 m-groups of 32 rows
    int nc0 = (w & 1) * 64;        // 2 n-groups of 64 cols

    float acc[2][8][4];
    #pragma unroll
    for (int mt = 0; mt < 2; mt++)
        #pragma unroll
        for (int nt = 0; nt < 8; nt++)
            #pragma unroll
            for (int j = 0; j < 4; j++) acc[mt][nt][j] = 0.f;

    const __half* ap = As + (mr + g) * SA + 2 * tg;
    const __half* bp = Bs + (nc0 + g) * SB + 2 * tg;

    #pragma unroll
    for (int ks = 0; ks < 128; ks += 16) {
        unsigned a[2][4];
        #pragma unroll
        for (int mt = 0; mt < 2; mt++) {
            const __half* amt = ap + mt * 16 * SA;
            a[mt][0] = *(const unsigned*)(amt + ks);
            a[mt][1] = *(const unsigned*)(amt + 8 * SA + ks);
            a[mt][2] = *(const unsigned*)(amt + ks + 8);
            a[mt][3] = *(const unsigned*)(amt + 8 * SA + ks + 8);
        }
        #pragma unroll
        for (int nt = 0; nt < 8; nt++) {
            unsigned b0 = *(const unsigned*)(bp + nt * 8 * SB + ks);
            unsigned b1 = *(const unsigned*)(bp + nt * 8 * SB + ks + 8);
            mma16816(acc[0][nt][0], acc[0][nt][1], acc[0][nt][2], acc[0][nt][3],
                     a[0][0], a[0][1], a[0][2], a[0][3], b0, b1);
            mma16816(acc[1][nt][0], acc[1][nt][1], acc[1][nt][2], acc[1][nt][3],
                     a[1][0], a[1][1], a[1][2], a[1][3], b0, b1);
        }
    }

    float sl[2][2] = {{0.f, 0.f}, {0.f, 0.f}};
    float sr[2][2] = {{0.f, 0.f}, {0.f, 0.f}};
    #pragma unroll
    for (int mt = 0; mt < 2; mt++) {
        int row_a = row0 + mr + mt * 16 + g;
        int row_b = row_a + 8;
        #pragma unroll
        for (int nt = 0; nt < 8; nt++) {
            int c0 = nc0 + nt * 8 + 2 * tg;
            float av0 = __ldg(&al[c0]), av1 = __ldg(&al[c0 + 1]);
            float rv0 = __ldg(&ar[c0]), rv1 = __ldg(&ar[c0 + 1]);
            sl[mt][0] += acc[mt][nt][0] * av0 + acc[mt][nt][1] * av1;
            sr[mt][0] += acc[mt][nt][0] * rv0 + acc[mt][nt][1] * rv1;
            sl[mt][1] += acc[mt][nt][2] * av0 + acc[mt][nt][3] * av1;
            sr[mt][1] += acc[mt][nt][2] * rv0 + acc[mt][nt][3] * rv1;
            if (row_a < M)
                *(__half2*)(C16 + row_a * 128 + c0) =
                    __float22half2_rn(make_float2(acc[mt][nt][0], acc[mt][nt][1]));
            if (row_b < M)
                *(__half2*)(C16 + row_b * 128 + c0) =
                    __float22half2_rn(make_float2(acc[mt][nt][2], acc[mt][nt][3]));
        }
    }
    #pragma unroll
    for (int d = 1; d < 4; d <<= 1) {
        #pragma unroll
        for (int mt = 0; mt < 2; mt++) {
            sl[mt][0] += __shfl_xor_sync(0xffffffffu, sl[mt][0], d);
            sr[mt][0] += __shfl_xor_sync(0xffffffffu, sr[mt][0], d);
            sl[mt][1] += __shfl_xor_sync(0xffffffffu, sl[mt][1], d);
            sr[mt][1] += __shfl_xor_sync(0xffffffffu, sr[mt][1], d);
        }
    }
    if (tg == 0) {
        #pragma unroll
        for (int mt = 0; mt < 2; mt++) {
            redl[w][mt * 16 + g]     = sl[mt][0];
            redl[w][mt * 16 + 8 + g] = sl[mt][1];
            redr[w][mt * 16 + g]     = sr[mt][0];
            redr[w][mt * 16 + 8 + g] = sr[mt][1];
        }
    }
    __syncthreads();
    if ((w & 1) == 0) {
        int row = row0 + mr + lane;
        if (row < M) {
            el[row] = redl[w][lane] + redl[w + 1][lane];
            er[row] = redr[w][lane] + redr[w + 1][lane];
        }
    }
}

// ======================= aggregation H=128: chunked, warp per node =========
__global__ void agg128_kernel(const __half* __restrict__ ft, const float* __restrict__ el,
                              const float* __restrict__ er, const int* __restrict__ off,
                              const unsigned short* __restrict__ csrc,
                              const float* __restrict__ bias,
                              __half* __restrict__ out, int* __restrict__ pos, int n) {
    int gw = (blockIdx.x * blockDim.x + threadIdx.x) >> 5;
    if (gw >= n) return;
    int lane = threadIdx.x & 31;
    if (lane == 0) pos[gw] = 0;              // re-zero for next replay's hist
    int beg = off[gw], end = off[gw + 1];
    float erd = __ldg(&er[gw]);
    float ssum = 0.f;
    float4 acc = make_float4(0.f, 0.f, 0.f, 0.f);
    const float2* fb = (const float2*)ft;

    int j0 = beg;
    for (; j0 + 32 <= end; j0 += 32) {
        int sidx = (int)__ldg(&csrc[j0 + lane]);
        float e = __ldg(&el[sidx]) + erd;
        e = fmaxf(e, 0.2f * e);
        float w = __expf(e);
        ssum += w;
        #pragma unroll
        for (int t = 0; t < 32; t++) {
            float wt = __shfl_sync(0xffffffffu, w, t);
            int st = __shfl_sync(0xffffffffu, sidx, t);
            float2 p = __ldg(&fb[st * 32 + lane]);
            __half2 h0 = *(__half2*)&p.x;
            __half2 h1 = *(__half2*)&p.y;
            float2 f0 = __half22float2(h0);
            float2 f1 = __half22float2(h1);
            acc.x = fmaf(wt, f0.x, acc.x);
            acc.y = fmaf(wt, f0.y, acc.y);
            acc.z = fmaf(wt, f1.x, acc.z);
            acc.w = fmaf(wt, f1.y, acc.w);
        }
    }
    int rem = end - j0;
    if (rem > 0) {
        int sidx = 0; float w = 0.f;
        if (lane < rem) {
            sidx = (int)__ldg(&csrc[j0 + lane]);
            float e = __ldg(&el[sidx]) + erd;
            e = fmaxf(e, 0.2f * e);
            w = __expf(e);
        }
        ssum += w;
        for (int t = 0; t < rem; t++) {
            float wt = __shfl_sync(0xffffffffu, w, t);
            int st = __shfl_sync(0xffffffffu, sidx, t);
            float2 p = __ldg(&fb[st * 32 + lane]);
            __half2 h0 = *(__half2*)&p.x;
            __half2 h1 = *(__half2*)&p.y;
            float2 f0 = __half22float2(h0);
            float2 f1 = __half22float2(h1);
            acc.x = fmaf(wt, f0.x, acc.x);
            acc.y = fmaf(wt, f0.y, acc.y);
            acc.z = fmaf(wt, f1.x, acc.z);
            acc.w = fmaf(wt, f1.y, acc.w);
        }
    }
    #pragma unroll
    for (int d = 16; d; d >>= 1) ssum += __shfl_xor_sync(0xffffffffu, ssum, d);
    float inv = (ssum > 0.f) ? 1.f / ssum : 0.f;
    float4 bv = ((const float4*)bias)[lane];
    __half2 o0 = __float22half2_rn(make_float2(fmaxf(acc.x * inv + bv.x, 0.f),
                                               fmaxf(acc.y * inv + bv.y, 0.f)));
    __half2 o1 = __float22half2_rn(make_float2(fmaxf(acc.z * inv + bv.z, 0.f),
                                               fmaxf(acc.w * inv + bv.w, 0.f)));
    uint2 u;
    u.x = *(unsigned*)&o0; u.y = *(unsigned*)&o1;
    *(uint2*)(out + gw * 128 + lane * 4) = u;
}

// ======================= layer 3: GEMM 128->16 (A fp16) ==================
__global__ void __launch_bounds__(256) gemm16_kernel(const __half* __restrict__ A,
                                                     const float* __restrict__ W,
                                                     const float* __restrict__ al,
                                                     const float* __restrict__ ar,
                                                     __half* __restrict__ C16,
                                                     float* __restrict__ el,
                                                     float* __restrict__ er, int M) {
    __shared__ float Ws[128 * 16];
    __shared__ float As[16 * 128];
    __shared__ float als[16], ars[16];
    int tid = threadIdx.x;
    for (int i = tid; i < 2048; i += 256) Ws[i] = W[i];
    if (tid < 16) { als[tid] = al[tid]; ars[tid] = ar[tid]; }
    int node0 = blockIdx.x * 16;
    for (int i = tid; i < 1024; i += 256) {   // 16 rows x 64 half2
        int ln = i >> 6, c2 = i & 63;
        int node = node0 + ln;
        float2 v = make_float2(0.f, 0.f);
        if (node < M) v = __half22float2(*(const __half2*)(A + node * 128 + c2 * 2));
        *(float2*)(As + ln * 128 + c2 * 2) = v;
    }
    __syncthreads();
    int ln = tid >> 4, col = tid & 15;
    int node = node0 + ln;
    float acc = 0.f;
    #pragma unroll 8
    for (int k = 0; k < 128; k++)
        acc = fmaf(As[ln * 128 + k], Ws[k * 16 + col], acc);

    if (node < M) C16[node * 16 + col] = __float2half_rn(acc);
    float sl = acc * als[col];
    float sr = acc * ars[col];
    #pragma unroll
    for (int d = 1; d < 16; d <<= 1) {
        sl += __shfl_xor_sync(0xffffffffu, sl, d);
        sr += __shfl_xor_sync(0xffffffffu, sr, d);
    }
    if (col == 0 && node < M) { el[node] = sl; er[node] = sr; }
}

// ======================= aggregation NC=16 =======================
__global__ void agg16_kernel(const __half* __restrict__ ftc, const float* __restrict__ el,
                             const float* __restrict__ er, const int* __restrict__ off,
                             const unsigned short* __restrict__ csrc,
                             const float* __restrict__ bias,
                             float* __restrict__ out, int n) {
    int gw = (blockIdx.x * blockDim.x + threadIdx.x) >> 5;
    if (gw >= n) return;
    int lane = threadIdx.x & 31;
    int lh = lane & 15, sel = lane >> 4;
    int beg = off[gw], end = off[gw + 1];
    float erd = __ldg(&er[gw]);
    float ssum = 0.f, acc = 0.f;

    int j0 = beg;
    for (; j0 + 32 <= end; j0 += 32) {
        int sidx = (int)__ldg(&csrc[j0 + lane]);
        float e = __ldg(&el[sidx]) + erd;
        e = fmaxf(e, 0.2f * e);
        float w = __expf(e);
        ssum += w;
        #pragma unroll
        for (int t = 0; t < 32; t += 2) {
            int tt = t + sel;
            float wt = __shfl_sync(0xffffffffu, w, tt);
            int st = __shfl_sync(0xffffffffu, sidx, tt);
            float f = __half2float(__ldg(&ftc[st * 16 + lh]));
            acc = fmaf(wt, f, acc);
        }
    }
    int rem = end - j0;
    if (rem > 0) {
        int sidx = 0; float w = 0.f;
        if (lane < rem) {
            sidx = (int)__ldg(&csrc[j0 + lane]);
            float e = __ldg(&el[sidx]) + erd;
            e = fmaxf(e, 0.2f * e);
            w = __expf(e);
        }
        ssum += w;
        for (int t = 0; t < rem; t += 2) {
            int tt = t + sel;                 // tt may be == rem: its w is 0
            float wt = __shfl_sync(0xffffffffu, w, tt & 31);
            int st = __shfl_sync(0xffffffffu, sidx, tt & 31);
            float f = __half2float(__ldg(&ftc[st * 16 + lh]));
            acc = fmaf(wt, f, acc);
        }
    }
    #pragma unroll
    for (int d = 16; d; d >>= 1) ssum += __shfl_xor_sync(0xffffffffu, ssum, d);
    acc += __shfl_xor_sync(0xffffffffu, acc, 16);
    float inv = (ssum > 0.f) ? 1.f / ssum : 0.f;
    if (lane < 16)
        out[gw * 16 + lane] = fmaxf(acc * inv + bias[lane], 0.f);
}

// ======================= launch =======================
extern "C" void kernel_launch(void* const* d_in, const int* in_sizes, int n_in,
                              void* d_out, int out_size) {
    const float* feat = (const float*)d_in[0];
    const int*   src  = (const int*)d_in[1];
    const int*   dst  = (const int*)d_in[2];
    const float* W1   = (const float*)d_in[3];
    const float* al1  = (const float*)d_in[4];
    const float* ar1  = (const float*)d_in[5];
    const float* b1   = (const float*)d_in[6];
    const float* W2   = (const float*)d_in[7];
    const float* al2  = (const float*)d_in[8];
    const float* ar2  = (const float*)d_in[9];
    const float* b2   = (const float*)d_in[10];
    const float* W3   = (const float*)d_in[11];
    const float* al3  = (const float*)d_in[12];
    const float* ar3  = (const float*)d_in[13];
    const float* b3   = (const float*)d_in[14];

    int M = in_sizes[0] / HF;
    int E = in_sizes[1];

    __half *ft16, *ftc, *h, *wt1, *wt2;
    float *el, *er;
    int *off, *pos, *bsum;
    unsigned short *csrc;
    cudaGetSymbolAddress((void**)&ft16, g_ft16);
    cudaGetSymbolAddress((void**)&ftc,  g_ftc);
    cudaGetSymbolAddress((void**)&h,    g_h);
    cudaGetSymbolAddress((void**)&el,   g_el);
    cudaGetSymbolAddress((void**)&er,   g_er);
    cudaGetSymbolAddress((void**)&off,  g_off);
    cudaGetSymbolAddress((void**)&pos,  g_pos);
    cudaGetSymbolAddress((void**)&csrc, g_csrc);
    cudaGetSymbolAddress((void**)&bsum, g_bsum);
    cudaGetSymbolAddress((void**)&wt1,  g_wt1);
    cudaGetSymbolAddress((void**)&wt2,  g_wt2);

    cudaFuncSetAttribute(gemm128_kernel<float>,
                         cudaFuncAttributeMaxDynamicSharedMemorySize, GEMM_SMEM);
    cudaFuncSetAttribute(gemm128_kernel<__half>,
                         cudaFuncAttributeMaxDynamicSharedMemorySize, GEMM_SMEM);

    int nb = (M + 1023) / 1024;
    int gemm_blocks = (M + 127) / 128;
    int warp_blocks = (M * 32 + 255) / 256;

    // 0: fused wconv + hist (pos zeroed by previous replay's agg128 / module init)
    whist_kernel<<<64 + 1536, 256>>>(W1, W2, wt1, wt2, dst, pos, E);
    // 1: scan phase 1
    scan1_kernel<<<nb, 1024>>>(pos, off, bsum, M);
    // 2: scan phases 2+3 fused
    scan3_kernel<<<nb, 1024>>>(off, pos, bsum, M, nb);
    // 3: layer-1 GEMM — ncu's profiled slot
    gemm128_kernel<float><<<gemm_blocks, 256, GEMM_SMEM>>>(feat, wt1, al1, ar1, ft16, el, er, M);
    // 4: scatter
    scatter_kernel<<<1600, 256>>>(src, dst, pos, csrc, E);
    // 5: layer-1 aggregation (also re-zeroes pos)
    agg128_kernel<<<warp_blocks, 256>>>(ft16, el, er, off, csrc, b1, h, pos, M);
    // 6-7: layer 2
    gemm128_kernel<__half><<<gemm_blocks, 256, GEMM_SMEM>>>(h, wt2, al2, ar2, ft16, el, er, M);
    agg128_kernel<<<warp_blocks, 256>>>(ft16, el, er, off, csrc, b2, h, pos, M);
    // 8-9: layer 3
    gemm16_kernel<<<(M + 15) / 16, 256>>>(h, W3, al3, ar3, ftc, el, er, M);
    agg16_kernel<<<warp_blocks, 256>>>(ftc, el, er, off, csrc, b3, (float*)d_out, M);
}

// round 15
// speedup vs baseline: 1.0334x; 1.0309x over previous
#include <cuda_runtime.h>
#include <cuda_fp16.h>

#define N_NODES 50000
#define N_EDGES 1600000
#define HF 128
#define NC 16

// -------- scratch (device globals; no allocation allowed) --------
__device__ __half g_ft16[N_NODES * HF];   // post-GEMM features (layers 1/2), fp16
__device__ __half g_ftc[N_NODES * NC];    // layer-3 features, fp16
__device__ __half g_h[N_NODES * HF];      // layer outputs (fp16)
__device__ float  g_el[N_NODES];
__device__ float  g_er[N_NODES];
__device__ int    g_off[N_NODES + 1];
__device__ int    g_pos[N_NODES];         // zero-init at load; re-zeroed by agg128
__device__ unsigned short g_csrc[N_EDGES]; // src ids fit in 16 bits
__device__ int    g_bsum[256];
__device__ __half g_wt1[HF * HF];         // W1^T fp16 [n][k]
__device__ __half g_wt2[HF * HF];         // W2^T fp16 [n][k]

// ============ fused: W transpose/convert (blocks 0-63) + hist (rest) =======
__global__ void whist_kernel(const float* __restrict__ W1, const float* __restrict__ W2,
                             __half* __restrict__ Wt1, __half* __restrict__ Wt2,
                             const int* __restrict__ dst, int* __restrict__ cnt, int E) {
    if (blockIdx.x < 64) {
        int i = blockIdx.x * 256 + threadIdx.x;
        int nn = i >> 7, k = i & 127;
        Wt1[nn * 128 + k] = __float2half_rn(W1[k * 128 + nn]);
        Wt2[nn * 128 + k] = __float2half_rn(W2[k * 128 + nn]);
        return;
    }
    int bid = blockIdx.x - 64;
    int nb = gridDim.x - 64;
    int E4 = E >> 2;
    const int4* d4 = (const int4*)dst;
    for (int i = bid * blockDim.x + threadIdx.x; i < E4; i += nb * blockDim.x) {
        int4 d = __ldg(&d4[i]);
        atomicAdd(&cnt[d.x], 1);
        atomicAdd(&cnt[d.y], 1);
        atomicAdd(&cnt[d.z], 1);
        atomicAdd(&cnt[d.w], 1);
    }
    int base = E4 << 2;
    int t = bid * blockDim.x + threadIdx.x;
    if (t < (E - base)) atomicAdd(&cnt[dst[base + t]], 1);
}

// ======================= CSR build =======================

__global__ void scan1_kernel(const int* __restrict__ cnt, int* __restrict__ off,
                             int* __restrict__ bsum, int n) {
    __shared__ int wsum[32];
    int tid = threadIdx.x;
    int i = blockIdx.x * 1024 + tid;
    int lane = tid & 31, wid = tid >> 5;
    int v = (i < n) ? cnt[i] : 0;
    int x = v;
    #pragma unroll
    for (int d = 1; d < 32; d <<= 1) {
        int y = __shfl_up_sync(0xffffffffu, x, d);
        if (lane >= d) x += y;
    }
    if (lane == 31) wsum[wid] = x;
    __syncthreads();
    if (wid == 0) {
        int w = wsum[lane];
        #pragma unroll
        for (int d = 1; d < 32; d <<= 1) {
            int y = __shfl_up_sync(0xffffffffu, w, d);
            if (lane >= d) w += y;
        }
        wsum[lane] = w;
    }
    __syncthreads();
    int excl = x - v + (wid > 0 ? wsum[wid - 1] : 0);
    if (i < n) off[i] = excl;
    if (tid == 0) bsum[blockIdx.x] = wsum[31];
}

// phase 2+3 fused: each block locally scans bsum (nb<=64), then adds
__global__ void scan3_kernel(int* __restrict__ off, int* __restrict__ pos,
                             const int* __restrict__ bsum, int n, int nb) {
    __shared__ int sprefix;
    __shared__ int stotal;
    int tid = threadIdx.x;
    if (tid < 32) {
        int v0 = (tid < nb) ? bsum[tid] : 0;
        int v1 = (tid + 32 < nb) ? bsum[tid + 32] : 0;
        int x0 = v0;
        #pragma unroll
        for (int d = 1; d < 32; d <<= 1) {
            int y = __shfl_up_sync(0xffffffffu, x0, d);
            if ((tid & 31) >= d) x0 += y;
        }
        int sum0 = __shfl_sync(0xffffffffu, x0, 31);
        int x1 = v1;
        #pragma unroll
        for (int d = 1; d < 32; d <<= 1) {
            int y = __shfl_up_sync(0xffffffffu, x1, d);
            if ((tid & 31) >= d) x1 += y;
        }
        int sum1 = __shfl_sync(0xffffffffu, x1, 31);
        int b = blockIdx.x;
        int excl;
        if (b < 32) excl = __shfl_sync(0xffffffffu, x0 - v0, b);
        else        excl = sum0 + __shfl_sync(0xffffffffu, x1 - v1, b - 32);
        if (tid == 0) { sprefix = excl; stotal = sum0 + sum1; }
    }
    __syncthreads();
    int add = sprefix;
    int i = blockIdx.x * 1024 + tid;
    if (i < n) {
        int v = off[i] + add;
        off[i] = v;
        pos[i] = v;
    }
    if (blockIdx.x == 0 && tid == 0) off[n] = stotal;
}

__global__ void scatter_kernel(const int* __restrict__ src, const int* __restrict__ dst,
                               int* __restrict__ pos, unsigned short* __restrict__ csrc, int E) {
    int E4 = E >> 2;
    const int4* s4 = (const int4*)src;
    const int4* d4 = (const int4*)dst;
    for (int i = blockIdx.x * blockDim.x + threadIdx.x; i < E4; i += gridDim.x * blockDim.x) {
        int4 s = __ldg(&s4[i]);
        int4 d = __ldg(&d4[i]);
        int p0 = atomicAdd(&pos[d.x], 1);
        int p1 = atomicAdd(&pos[d.y], 1);
        int p2 = atomicAdd(&pos[d.z], 1);
        int p3 = atomicAdd(&pos[d.w], 1);
        csrc[p0] = (unsigned short)s.x;
        csrc[p1] = (unsigned short)s.y;
        csrc[p2] = (unsigned short)s.z;
        csrc[p3] = (unsigned short)s.w;
    }
    int base = E4 << 2;
    int t = blockIdx.x * blockDim.x + threadIdx.x;
    if (t < (E - base)) {
        int p = atomicAdd(&pos[dst[base + t]], 1);
        csrc[p] = (unsigned short)src[base + t];
    }
}

// ======================= GEMM 128x128 via HMMA fp16/f32 (R12 frozen) =======
#define SA 136
#define SB 136
#define GEMM_SMEM ((128 * SA + 128 * SB) * 2)

__device__ __forceinline__ void mma16816(float& d0, float& d1, float& d2, float& d3,
                                         unsigned a0, unsigned a1, unsigned a2, unsigned a3,
                                         unsigned b0, unsigned b1) {
    asm volatile("mma.sync.aligned.m16n8k16.row.col.f32.f16.f16.f32 "
                 "{%0,%1,%2,%3}, {%4,%5,%6,%7}, {%8,%9}, {%0,%1,%2,%3};"
                 : "+f"(d0), "+f"(d1), "+f"(d2), "+f"(d3)
                 : "r"(a0), "r"(a1), "r"(a2), "r"(a3), "r"(b0), "r"(b1));
}

template <typename T>
__global__ void __launch_bounds__(256) gemm128_kernel(
    const T* __restrict__ A, const __half* __restrict__ Wt,
    const float* __restrict__ al, const float* __restrict__ ar,
    __half* __restrict__ C16, float* __restrict__ el, float* __restrict__ er, int M) {
    extern __shared__ __half smh[];
    __half* As = smh;              // [m][k], stride SA
    __half* Bs = smh + 128 * SA;   // [n][k], stride SB
    int tid = threadIdx.x;
    int row0 = blockIdx.x * 128;

    // stage Wt (fp16 global, coalesced 16B)
    for (int i = tid; i < 2048; i += 256) {
        int n = i >> 4, k8 = (i & 15) * 8;
        uint4 v = *(const uint4*)(Wt + n * 128 + k8);
        *(uint4*)(Bs + n * SB + k8) = v;
    }
    // stage A
    if (sizeof(T) == 4) {          // fp32 input: convert while staging
        const float* Af = (const float*)A;
        for (int i = tid; i < 4096; i += 256) {
            int r = i >> 5, c = (i & 31) * 4;
            int gr = row0 + r;
            float4 v = make_float4(0.f, 0.f, 0.f, 0.f);
            if (gr < M) v = *(const float4*)(Af + gr * 128 + c);
            *(__half2*)(As + r * SA + c)     = __float22half2_rn(make_float2(v.x, v.y));
            *(__half2*)(As + r * SA + c + 2) = __float22half2_rn(make_float2(v.z, v.w));
        }
    } else {                       // fp16 input: straight 16B copy
        const __half* Ah = (const __half*)A;
        for (int i = tid; i < 2048; i += 256) {
            int r = i >> 4, c = (i & 15) * 8;
            int gr = row0 + r;
            uint4 v = make_uint4(0u, 0u, 0u, 0u);
            if (gr < M) v = *(const uint4*)(Ah + gr * 128 + c);
            *(uint4*)(As + r * SA + c) = v;
        }
    }
    __syncthreads();

    int w = tid >> 5, lane = tid & 31;
    int g = lane >> 2, tg = lane & 3;
    int mr = w * 16;

    float acc[16][4];
    #pragma unroll
    for (int nt = 0; nt < 16; nt++)
        #pragma unroll
        for (int j = 0; j < 4; j++) acc[nt][j] = 0.f;

    const __half* ap0 = As + (mr + g) * SA + 2 * tg;
    const __half* ap1 = ap0 + 8 * SA;
    const __half* bp  = Bs + g * SB + 2 * tg;

    #pragma unroll
    for (int ks = 0; ks < 128; ks += 16) {
        unsigned a0 = *(const unsigned*)(ap0 + ks);
        unsigned a1 = *(const unsigned*)(ap1 + ks);
        unsigned a2 = *(const unsigned*)(ap0 + ks + 8);
        unsigned a3 = *(const unsigned*)(ap1 + ks + 8);
        #pragma unroll
        for (int nt = 0; nt < 16; nt++) {
            unsigned b0 = *(const unsigned*)(bp + nt * 8 * SB + ks);
            unsigned b1 = *(const unsigned*)(bp + nt * 8 * SB + ks + 8);
            mma16816(acc[nt][0], acc[nt][1], acc[nt][2], acc[nt][3],
                     a0, a1, a2, a3, b0, b1);
        }
    }

    int row_a = row0 + mr + g;
    int row_b = row_a + 8;
    float sl0 = 0.f, sr0 = 0.f, sl1 = 0.f, sr1 = 0.f;
    #pragma unroll
    for (int nt = 0; nt < 16; nt++) {
        int c0 = nt * 8 + 2 * tg;
        float av0 = __ldg(&al[c0]), av1 = __ldg(&al[c0 + 1]);
        float rv0 = __ldg(&ar[c0]), rv1 = __ldg(&ar[c0 + 1]);
        sl0 += acc[nt][0] * av0 + acc[nt][1] * av1;
        sr0 += acc[nt][0] * rv0 + acc[nt][1] * rv1;
        sl1 += acc[nt][2] * av0 + acc[nt][3] * av1;
        sr1 += acc[nt][2] * rv0 + acc[nt][3] * rv1;
        if (row_a < M)
            *(__half2*)(C16 + row_a * 128 + c0) =
                __float22half2_rn(make_float2(acc[nt][0], acc[nt][1]));
        if (row_b < M)
            *(__half2*)(C16 + row_b * 128 + c0) =
                __float22half2_rn(make_float2(acc[nt][2], acc[nt][3]));
    }
    #pragma unroll
    for (int d = 1; d < 4; d <<= 1) {
        sl0 += __shfl_xor_sync(0xffffffffu, sl0, d);
        sr0 += __shfl_xor_sync(0xffffffffu, sr0, d);
        sl1 += __shfl_xor_sync(0xffffffffu, sl1, d);
        sr1 += __shfl_xor_sync(0xffffffffu, sr1, d);
    }
    if (tg == 0) {
        if (row_a < M) { el[row_a] = sl0; er[row_a] = sr0; }
        if (row_b < M) { el[row_b] = sl1; er[row_b] = sr1; }
    }
}

// ======================= aggregation H=128: chunked, warp per node =========
__global__ void agg128_kernel(const __half* __restrict__ ft, const float* __restrict__ el,
                              const float* __restrict__ er, const int* __restrict__ off,
                              const unsigned short* __restrict__ csrc,
                              const float* __restrict__ bias,
                              __half* __restrict__ out, int* __restrict__ pos, int n) {
    int gw = (blockIdx.x * blockDim.x + threadIdx.x) >> 5;
    if (gw >= n) return;
    int lane = threadIdx.x & 31;
    if (lane == 0) pos[gw] = 0;              // re-zero for next replay's hist
    int beg = off[gw], end = off[gw + 1];
    float erd = __ldg(&er[gw]);
    float ssum = 0.f;
    float4 acc = make_float4(0.f, 0.f, 0.f, 0.f);
    const float2* fb = (const float2*)ft;

    int j0 = beg;
    for (; j0 + 32 <= end; j0 += 32) {
        int sidx = (int)__ldg(&csrc[j0 + lane]);
        float e = __ldg(&el[sidx]) + erd;
        e = fmaxf(e, 0.2f * e);
        float w = __expf(e);
        ssum += w;
        #pragma unroll
        for (int t = 0; t < 32; t++) {
            float wt = __shfl_sync(0xffffffffu, w, t);
            int st = __shfl_sync(0xffffffffu, sidx, t);
            float2 p = __ldg(&fb[st * 32 + lane]);
            __half2 h0 = *(__half2*)&p.x;
            __half2 h1 = *(__half2*)&p.y;
            float2 f0 = __half22float2(h0);
            float2 f1 = __half22float2(h1);
            acc.x = fmaf(wt, f0.x, acc.x);
            acc.y = fmaf(wt, f0.y, acc.y);
            acc.z = fmaf(wt, f1.x, acc.z);
            acc.w = fmaf(wt, f1.y, acc.w);
        }
    }
    int rem = end - j0;
    if (rem > 0) {
        int sidx = 0; float w = 0.f;
        if (lane < rem) {
            sidx = (int)__ldg(&csrc[j0 + lane]);
            float e = __ldg(&el[sidx]) + erd;
            e = fmaxf(e, 0.2f * e);
            w = __expf(e);
        }
        ssum += w;
        for (int t = 0; t < rem; t++) {
            float wt = __shfl_sync(0xffffffffu, w, t);
            int st = __shfl_sync(0xffffffffu, sidx, t);
            float2 p = __ldg(&fb[st * 32 + lane]);
            __half2 h0 = *(__half2*)&p.x;
            __half2 h1 = *(__half2*)&p.y;
            float2 f0 = __half22float2(h0);
            float2 f1 = __half22float2(h1);
            acc.x = fmaf(wt, f0.x, acc.x);
            acc.y = fmaf(wt, f0.y, acc.y);
            acc.z = fmaf(wt, f1.x, acc.z);
            acc.w = fmaf(wt, f1.y, acc.w);
        }
    }
    #pragma unroll
    for (int d = 16; d; d >>= 1) ssum += __shfl_xor_sync(0xffffffffu, ssum, d);
    float inv = (ssum > 0.f) ? 1.f / ssum : 0.f;
    float4 bv = ((const float4*)bias)[lane];
    __half2 o0 = __float22half2_rn(make_float2(fmaxf(acc.x * inv + bv.x, 0.f),
                                               fmaxf(acc.y * inv + bv.y, 0.f)));
    __half2 o1 = __float22half2_rn(make_float2(fmaxf(acc.z * inv + bv.z, 0.f),
                                               fmaxf(acc.w * inv + bv.w, 0.f)));
    uint2 u;
    u.x = *(unsigned*)&o0; u.y = *(unsigned*)&o1;
    *(uint2*)(out + gw * 128 + lane * 4) = u;
}

// ======================= layer 3: GEMM 128->16 (A fp16) ==================
__global__ void __launch_bounds__(256) gemm16_kernel(const __half* __restrict__ A,
                                                     const float* __restrict__ W,
                                                     const float* __restrict__ al,
                                                     const float* __restrict__ ar,
                                                     __half* __restrict__ C16,
                                                     float* __restrict__ el,
                                                     float* __restrict__ er, int M) {
    __shared__ float Ws[128 * 16];
    __shared__ float As[16 * 128];
    __shared__ float als[16], ars[16];
    int tid = threadIdx.x;
    for (int i = tid; i < 2048; i += 256) Ws[i] = W[i];
    if (tid < 16) { als[tid] = al[tid]; ars[tid] = ar[tid]; }
    int node0 = blockIdx.x * 16;
    for (int i = tid; i < 1024; i += 256) {   // 16 rows x 64 half2
        int ln = i >> 6, c2 = i & 63;
        int node = node0 + ln;
        float2 v = make_float2(0.f, 0.f);
        if (node < M) v = __half22float2(*(const __half2*)(A + node * 128 + c2 * 2));
        *(float2*)(As + ln * 128 + c2 * 2) = v;
    }
    __syncthreads();
    int ln = tid >> 4, col = tid & 15;
    int node = node0 + ln;
    float acc = 0.f;
    #pragma unroll 8
    for (int k = 0; k < 128; k++)
        acc = fmaf(As[ln * 128 + k], Ws[k * 16 + col], acc);

    if (node < M) C16[node * 16 + col] = __float2half_rn(acc);
    float sl = acc * als[col];
    float sr = acc * ars[col];
    #pragma unroll
    for (int d = 1; d < 16; d <<= 1) {
        sl += __shfl_xor_sync(0xffffffffu, sl, d);
        sr += __shfl_xor_sync(0xffffffffu, sr, d);
    }
    if (col == 0 && node < M) { el[node] = sl; er[node] = sr; }
}

// ======================= aggregation NC=16 =======================
__global__ void agg16_kernel(const __half* __restrict__ ftc, const float* __restrict__ el,
                             const float* __restrict__ er, const int* __restrict__ off,
                             const unsigned short* __restrict__ csrc,
                             const float* __restrict__ bias,
                             float* __restrict__ out, int n) {
    int gw = (blockIdx.x * blockDim.x + threadIdx.x) >> 5;
    if (gw >= n) return;
    int lane = threadIdx.x & 31;
    int lh = lane & 15, sel = lane >> 4;
    int beg = off[gw], end = off[gw + 1];
    float erd = __ldg(&er[gw]);
    float ssum = 0.f, acc = 0.f;

    int j0 = beg;
    for (; j0 + 32 <= end; j0 += 32) {
        int sidx = (int)__ldg(&csrc[j0 + lane]);
        float e = __ldg(&el[sidx]) + erd;
        e = fmaxf(e, 0.2f * e);
        float w = __expf(e);
        ssum += w;
        #pragma unroll
        for (int t = 0; t < 32; t += 2) {
            int tt = t + sel;
            float wt = __shfl_sync(0xffffffffu, w, tt);
            int st = __shfl_sync(0xffffffffu, sidx, tt);
            float f = __half2float(__ldg(&ftc[st * 16 + lh]));
            acc = fmaf(wt, f, acc);
        }
    }
    int rem = end - j0;
    if (rem > 0) {
        int sidx = 0; float w = 0.f;
        if (lane < rem) {
            sidx = (int)__ldg(&csrc[j0 + lane]);
            float e = __ldg(&el[sidx]) + erd;
            e = fmaxf(e, 0.2f * e);
            w = __expf(e);
        }
        ssum += w;
        for (int t = 0; t < rem; t += 2) {
            int tt = t + sel;                 // tt may be == rem: its w is 0
            float wt = __shfl_sync(0xffffffffu, w, tt & 31);
            int st = __shfl_sync(0xffffffffu, sidx, tt & 31);
            float f = __half2float(__ldg(&ftc[st * 16 + lh]));
            acc = fmaf(wt, f, acc);
        }
    }
    #pragma unroll
    for (int d = 16; d; d >>= 1) ssum += __shfl_xor_sync(0xffffffffu, ssum, d);
    acc += __shfl_xor_sync(0xffffffffu, acc, 16);
    float inv = (ssum > 0.f) ? 1.f / ssum : 0.f;
    if (lane < 16)
        out[gw * 16 + lane] = fmaxf(acc * inv + bias[lane], 0.f);
}

// ======================= launch =======================
extern "C" void kernel_launch(void* const* d_in, const int* in_sizes, int n_in,
                              void* d_out, int out_size) {
    const float* feat = (const float*)d_in[0];
    const int*   src  = (const int*)d_in[1];
    const int*   dst  = (const int*)d_in[2];
    const float* W1   = (const float*)d_in[3];
    const float* al1  = (const float*)d_in[4];
    const float* ar1  = (const float*)d_in[5];
    const float* b1   = (const float*)d_in[6];
    const float* W2   = (const float*)d_in[7];
    const float* al2  = (const float*)d_in[8];
    const float* ar2  = (const float*)d_in[9];
    const float* b2   = (const float*)d_in[10];
    const float* W3   = (const float*)d_in[11];
    const float* al3  = (const float*)d_in[12];
    const float* ar3  = (const float*)d_in[13];
    const float* b3   = (const float*)d_in[14];

    int M = in_sizes[0] / HF;
    int E = in_sizes[1];

    __half *ft16, *ftc, *h, *wt1, *wt2;
    float *el, *er;
    int *off, *pos, *bsum;
    unsigned short *csrc;
    cudaGetSymbolAddress((void**)&ft16, g_ft16);
    cudaGetSymbolAddress((void**)&ftc,  g_ftc);
    cudaGetSymbolAddress((void**)&h,    g_h);
    cudaGetSymbolAddress((void**)&el,   g_el);
    cudaGetSymbolAddress((void**)&er,   g_er);
    cudaGetSymbolAddress((void**)&off,  g_off);
    cudaGetSymbolAddress((void**)&pos,  g_pos);
    cudaGetSymbolAddress((void**)&csrc, g_csrc);
    cudaGetSymbolAddress((void**)&bsum, g_bsum);
    cudaGetSymbolAddress((void**)&wt1,  g_wt1);
    cudaGetSymbolAddress((void**)&wt2,  g_wt2);

    cudaFuncSetAttribute(gemm128_kernel<float>,
                         cudaFuncAttributeMaxDynamicSharedMemorySize, GEMM_SMEM);
    cudaFuncSetAttribute(gemm128_kernel<__half>,
                         cudaFuncAttributeMaxDynamicSharedMemorySize, GEMM_SMEM);
    // request max shared-memory carveout so a 3rd 70.8KB block can co-reside
    cudaFuncSetAttribute(gemm128_kernel<float>,
                         cudaFuncAttributePreferredSharedMemoryCarveout, 100);
    cudaFuncSetAttribute(gemm128_kernel<__half>,
                         cudaFuncAttributePreferredSharedMemoryCarveout, 100);

    int nb = (M + 1023) / 1024;
    int gemm_blocks = (M + 127) / 128;
    int warp_blocks = (M * 32 + 255) / 256;

    // 0: fused wconv + hist (pos zeroed by previous replay's agg128 / module init)
    whist_kernel<<<64 + 1536, 256>>>(W1, W2, wt1, wt2, dst, pos, E);
    // 1: scan phase 1
    scan1_kernel<<<nb, 1024>>>(pos, off, bsum, M);
    // 2: scan phases 2+3 fused
    scan3_kernel<<<nb, 1024>>>(off, pos, bsum, M, nb);
    // 3: layer-1 GEMM — ncu's profiled slot
    gemm128_kernel<float><<<gemm_blocks, 256, GEMM_SMEM>>>(feat, wt1, al1, ar1, ft16, el, er, M);
    // 4: scatter
    scatter_kernel<<<1600, 256>>>(src, dst, pos, csrc, E);
    // 5: layer-1 aggregation (also re-zeroes pos)
    agg128_kernel<<<warp_blocks, 256>>>(ft16, el, er, off, csrc, b1, h, pos, M);
    // 6-7: layer 2
    gemm128_kernel<__half><<<gemm_blocks, 256, GEMM_SMEM>>>(h, wt2, al2, ar2, ft16, el, er, M);
    agg128_kernel<<<warp_blocks, 256>>>(ft16, el, er, off, csrc, b2, h, pos, M);
    // 8-9: layer 3
    gemm16_kernel<<<(M + 15) / 16, 256>>>(h, W3, al3, ar3, ftc, el, er, M);
    agg16_kernel<<<warp_blocks, 256>>>(ftc, el, er, off, csrc, b3, (float*)d_out, M);
}